// round 9
// baseline (speedup 1.0000x reference)
#include <cuda_runtime.h>
#include <math.h>
#include <stdint.h>

#define CDIM 1024
#define NSEQ 2048
#define NHEAD 16
#define HDIM 64
#define RS 3072
#define QK_SCALE 0.125f

__device__ float g_qkv[25165824];   // [8192][3072] qkv scratch

__device__ __forceinline__ uint32_t smem_u32(const void* p) {
    return (uint32_t)__cvta_generic_to_shared(p);
}
__device__ __forceinline__ uint32_t f2tf32(float f) {
    uint32_t r;
    asm("cvt.rna.tf32.f32 %0, %1;" : "=r"(r) : "f"(f));
    return r;
}

#define MMA_TF32(d, a, b0, b1) \
    asm volatile( \
        "mma.sync.aligned.m16n8k8.row.col.f32.tf32.tf32.f32 " \
        "{%0,%1,%2,%3}, {%4,%5,%6,%7}, {%8,%9}, {%0,%1,%2,%3};" \
        : "+f"((d)[0]), "+f"((d)[1]), "+f"((d)[2]), "+f"((d)[3]) \
        : "r"((a)[0]), "r"((a)[1]), "r"((a)[2]), "r"((a)[3]), \
          "r"(b0), "r"(b1))

// ============================================================================
// Kernel 1: mma.sync tf32 GEMM, 2-pass split (unchanged, proven).
// ============================================================================
#define SROW 36
#define STAGE_F (2 * 128 * SROW)
#define GEMM_DSMEM (3 * STAGE_F * 4)

__global__ __launch_bounds__(256, 1) void qkv_gemm_tc(
    const float* __restrict__ X, const float* __restrict__ W,
    const float* __restrict__ bias)
{
    extern __shared__ float smg[];
    const int t    = threadIdx.x;
    const int wid  = t >> 5;
    const int lane = t & 31;
    const int gid  = lane >> 2;
    const int tig  = lane & 3;
    const int wm   = wid >> 2;
    const int wn   = wid & 3;
    const int bm   = blockIdx.y * 128;
    const int bn   = blockIdx.x * 128;

    float acc[4][4][4];
    #pragma unroll
    for (int mi = 0; mi < 4; mi++)
        #pragma unroll
        for (int ni = 0; ni < 4; ni++)
            #pragma unroll
            for (int r = 0; r < 4; r++) acc[mi][ni][r] = 0.0f;

    const int lrow = t >> 3;
    const int lc4  = t & 7;

    auto load_stage = [&](int s) {
        float* A  = smg + (s % 3) * STAGE_F;
        const uint32_t ab = smem_u32(A);
        const uint32_t bb = ab + 128 * SROW * 4;
        #pragma unroll
        for (int i = 0; i < 4; i++) {
            const int row = i * 32 + lrow;
            const uint32_t so = (uint32_t)(row * (SROW * 4) + lc4 * 16);
            const float* sa = X + (size_t)(bm + row) * CDIM + s * 32 + lc4 * 4;
            const float* sw = W + (size_t)(bn + row) * CDIM + s * 32 + lc4 * 4;
            asm volatile("cp.async.cg.shared.global [%0], [%1], 16;"
                         :: "r"(ab + so), "l"(sa) : "memory");
            asm volatile("cp.async.cg.shared.global [%0], [%1], 16;"
                         :: "r"(bb + so), "l"(sw) : "memory");
        }
        asm volatile("cp.async.commit_group;" ::: "memory");
    };

    load_stage(0);
    load_stage(1);

    for (int kt = 0; kt < CDIM / 32; kt++) {
        asm volatile("cp.async.wait_group 1;" ::: "memory");
        __syncthreads();

        if (kt + 2 < CDIM / 32) load_stage(kt + 2);
        else asm volatile("cp.async.commit_group;" ::: "memory");

        const float* A  = smg + (kt % 3) * STAGE_F;
        const float* Bs = A + 128 * SROW;

        #pragma unroll
        for (int ks = 0; ks < 4; ks++) {
            const int k0 = ks * 8 + tig;
            uint32_t ahi[4][4], alo[4][4], bhi[4][2];
            #pragma unroll
            for (int mi = 0; mi < 4; mi++) {
                const int r0 = (wm * 64 + mi * 16 + gid) * SROW;
                float a0 = A[r0 + k0];
                float a1 = A[r0 + 8 * SROW + k0];
                float a2 = A[r0 + k0 + 4];
                float a3 = A[r0 + 8 * SROW + k0 + 4];
                ahi[mi][0] = f2tf32(a0); alo[mi][0] = f2tf32(a0 - __uint_as_float(ahi[mi][0]));
                ahi[mi][1] = f2tf32(a1); alo[mi][1] = f2tf32(a1 - __uint_as_float(ahi[mi][1]));
                ahi[mi][2] = f2tf32(a2); alo[mi][2] = f2tf32(a2 - __uint_as_float(ahi[mi][2]));
                ahi[mi][3] = f2tf32(a3); alo[mi][3] = f2tf32(a3 - __uint_as_float(ahi[mi][3]));
            }
            #pragma unroll
            for (int ni = 0; ni < 4; ni++) {
                const int n0 = (wn * 32 + ni * 8 + gid) * SROW;
                bhi[ni][0] = f2tf32(Bs[n0 + k0]);
                bhi[ni][1] = f2tf32(Bs[n0 + k0 + 4]);
            }
            #pragma unroll
            for (int mi = 0; mi < 4; mi++)
                #pragma unroll
                for (int ni = 0; ni < 4; ni++) {
                    MMA_TF32(acc[mi][ni], ahi[mi], bhi[ni][0], bhi[ni][1]);
                    MMA_TF32(acc[mi][ni], alo[mi], bhi[ni][0], bhi[ni][1]);
                }
        }
        __syncthreads();
    }

    const float cs = (bn < CDIM) ? QK_SCALE : 1.0f;
    #pragma unroll
    for (int mi = 0; mi < 4; mi++) {
        const int r0 = bm + wm * 64 + mi * 16 + gid;
        #pragma unroll
        for (int ni = 0; ni < 4; ni++) {
            const int c = bn + wn * 32 + ni * 8 + tig * 2;
            const float b0 = bias[c], b1 = bias[c + 1];
            float2 v0, v1;
            v0.x = (acc[mi][ni][0] + b0) * cs;
            v0.y = (acc[mi][ni][1] + b1) * cs;
            v1.x = (acc[mi][ni][2] + b0) * cs;
            v1.y = (acc[mi][ni][3] + b1) * cs;
            *(float2*)(g_qkv + (size_t)r0 * RS + c)       = v0;
            *(float2*)(g_qkv + (size_t)(r0 + 8) * RS + c) = v1;
        }
    }
}

// ============================================================================
// Kernel 2: tensor-core flash attention, v3.
// 128 threads (4 warps), 64 q-rows per CTA, 89KB smem -> 2 CTAs/SM so the
// two co-resident CTAs' softmax/MMA phases interleave (independent barriers).
// QK: 1-pass, Q rounded tf32 (regs), K raw f32 (truncated by MMA).
// PV: 1-pass, P rounded tf32, V raw. Epilogue corrects V-truncation bias.
// smem u32: K[2][64][68], V[2][64][72], Phi [64][68] (Q staged in Phi).
// ============================================================================
#define K0_OFF 0
#define K1_OFF 4352
#define V0_OFF 8704
#define V1_OFF 13312
#define PHI_OFF 17920
#define ATTN_DSMEM (22272 * 4)   // 89088 bytes

__global__ __launch_bounds__(128, 2) void attn_tc(float* __restrict__ out)
{
    extern __shared__ uint32_t sb[];
    uint32_t* Phi = sb + PHI_OFF;
    float*    Qs  = (float*)Phi;              // staging view [64][65]

    const int tid  = threadIdx.x;
    const int wid  = tid >> 5;
    const int lane = tid & 31;
    const int r    = lane >> 2;
    const int tig  = lane & 3;
    const int bh   = blockIdx.y;
    const int b    = bh >> 4;
    const int h    = bh & 15;
    const int q0   = blockIdx.x << 6;

    const float* Qg = g_qkv + (size_t)(b * NSEQ) * RS + h * HDIM;
    const float* Kg = Qg + CDIM;
    const float* Vg = Qg + 2 * CDIM;

    const uint32_t sbase = smem_u32(sb);
    const uint32_t kb0 = sbase + K0_OFF * 4, kb1 = sbase + K1_OFF * 4;
    const uint32_t vb0 = sbase + V0_OFF * 4, vb1 = sbase + V1_OFF * 4;

    // ---- double-buffered raw K/V tile copy (64 keys x 64 dims) ----
    auto issue_tile = [&](int t) {
        const int key0 = t << 6;
        const uint32_t kbb = (t & 1) ? kb1 : kb0;
        const uint32_t vbb = (t & 1) ? vb1 : vb0;
        #pragma unroll
        for (int j = 0; j < 8; j++) {
            const int idx = j * 128 + tid;      // 1024 chunks of 16B per tensor
            const int row = idx >> 4;
            const int ch  = (idx & 15) << 2;
            const float* ks = Kg + (size_t)(key0 + row) * RS + ch;
            const float* vs = Vg + (size_t)(key0 + row) * RS + ch;
            asm volatile("cp.async.cg.shared.global [%0], [%1], 16;"
                         :: "r"(kbb + (uint32_t)(row * 68 + ch) * 4), "l"(ks) : "memory");
            asm volatile("cp.async.cg.shared.global [%0], [%1], 16;"
                         :: "r"(vbb + (uint32_t)(row * 72 + ch) * 4), "l"(vs) : "memory");
        }
        asm volatile("cp.async.commit_group;" ::: "memory");
    };

    issue_tile(0);

    // ---- stage Q (f32) into Phi region ----
    #pragma unroll
    for (int i = 0; i < 8; i++) {
        const int idx = i * 128 + tid;          // 1024 float4s
        const int row = idx >> 4;
        const int c4  = (idx & 15) << 2;
        float4 v = *(const float4*)(Qg + (size_t)(q0 + row) * RS + c4);
        float* d = Qs + row * 65 + c4;
        d[0] = v.x; d[1] = v.y; d[2] = v.z; d[3] = v.w;
    }
    __syncthreads();

    // ---- Q frags (rounded tf32) into registers ----
    const int R0 = wid << 4;
    uint32_t qhi[8][4];
    #pragma unroll
    for (int kt = 0; kt < 8; kt++) {
        const int k0 = kt * 8 + tig;
        qhi[kt][0] = f2tf32(Qs[(R0 + r) * 65 + k0]);
        qhi[kt][1] = f2tf32(Qs[(R0 + r + 8) * 65 + k0]);
        qhi[kt][2] = f2tf32(Qs[(R0 + r) * 65 + k0 + 4]);
        qhi[kt][3] = f2tf32(Qs[(R0 + r + 8) * 65 + k0 + 4]);
    }

    float oacc[8][4];
    #pragma unroll
    for (int nt = 0; nt < 8; nt++)
        #pragma unroll
        for (int c = 0; c < 4; c++) oacc[nt][c] = 0.0f;
    float m0 = -1e30f, m1 = -1e30f, l0 = 0.0f, l1 = 0.0f;

    const int rl = R0 + r;
    const int rh = rl + 8;

    #pragma unroll 1
    for (int t = 0; t < NSEQ / 64; t++) {
        asm volatile("cp.async.wait_group 0;" ::: "memory");
        __syncthreads();            // tile t visible; buf (t+1)&1 free

        if (t + 1 < NSEQ / 64) issue_tile(t + 1);

        const uint32_t* Khi = sb + ((t & 1) ? K1_OFF : K0_OFF);
        const uint32_t* Vhi = sb + ((t & 1) ? V1_OFF : V0_OFF);

        // ---- S = Q @ K^T (1-pass, K raw) ----
        float sacc[8][4];
        #pragma unroll
        for (int nt = 0; nt < 8; nt++)
            #pragma unroll
            for (int c = 0; c < 4; c++) sacc[nt][c] = 0.0f;

        #pragma unroll
        for (int kt = 0; kt < 8; kt++) {
            const int k0 = kt * 8 + tig;
            #pragma unroll
            for (int nt = 0; nt < 8; nt++) {
                const int n0 = (nt * 8 + r) * 68;
                MMA_TF32(sacc[nt], qhi[kt], Khi[n0 + k0], Khi[n0 + k0 + 4]);
            }
        }

        // ---- online softmax ----
        float mx0 = -1e30f, mx1 = -1e30f;
        #pragma unroll
        for (int nt = 0; nt < 8; nt++) {
            mx0 = fmaxf(mx0, fmaxf(sacc[nt][0], sacc[nt][1]));
            mx1 = fmaxf(mx1, fmaxf(sacc[nt][2], sacc[nt][3]));
        }
        mx0 = fmaxf(mx0, __shfl_xor_sync(0xffffffffu, mx0, 1));
        mx0 = fmaxf(mx0, __shfl_xor_sync(0xffffffffu, mx0, 2));
        mx1 = fmaxf(mx1, __shfl_xor_sync(0xffffffffu, mx1, 1));
        mx1 = fmaxf(mx1, __shfl_xor_sync(0xffffffffu, mx1, 2));
        const float nm0 = fmaxf(m0, mx0), nm1 = fmaxf(m1, mx1);
        const float cr0 = __expf(m0 - nm0), cr1 = __expf(m1 - nm1);
        float sum0 = 0.0f, sum1 = 0.0f;
        #pragma unroll
        for (int nt = 0; nt < 8; nt++) {
            sacc[nt][0] = __expf(sacc[nt][0] - nm0);
            sacc[nt][1] = __expf(sacc[nt][1] - nm0);
            sacc[nt][2] = __expf(sacc[nt][2] - nm1);
            sacc[nt][3] = __expf(sacc[nt][3] - nm1);
            sum0 += sacc[nt][0] + sacc[nt][1];
            sum1 += sacc[nt][2] + sacc[nt][3];
        }
        sum0 += __shfl_xor_sync(0xffffffffu, sum0, 1);
        sum0 += __shfl_xor_sync(0xffffffffu, sum0, 2);
        sum1 += __shfl_xor_sync(0xffffffffu, sum1, 1);
        sum1 += __shfl_xor_sync(0xffffffffu, sum1, 2);
        l0 = l0 * cr0 + sum0; m0 = nm0;
        l1 = l1 * cr1 + sum1; m1 = nm1;
        #pragma unroll
        for (int nt = 0; nt < 8; nt++) {
            oacc[nt][0] *= cr0; oacc[nt][1] *= cr0;
            oacc[nt][2] *= cr1; oacc[nt][3] *= cr1;
        }

        // ---- P -> tf32 -> smem (warp-local rows) ----
        #pragma unroll
        for (int nt = 0; nt < 8; nt++) {
            const int c = nt * 8 + tig * 2;
            uint64_t p0 = (uint64_t)f2tf32(sacc[nt][0])
                        | ((uint64_t)f2tf32(sacc[nt][1]) << 32);
            uint64_t p1 = (uint64_t)f2tf32(sacc[nt][2])
                        | ((uint64_t)f2tf32(sacc[nt][3]) << 32);
            *(uint64_t*)(Phi + rl * 68 + c) = p0;
            *(uint64_t*)(Phi + rh * 68 + c) = p1;
        }
        __syncwarp();

        // ---- O += P @ V (V raw) ----
        #pragma unroll
        for (int kt = 0; kt < 8; kt++) {
            const int k0 = kt * 8 + tig;
            uint32_t a[4];
            a[0] = Phi[rl * 68 + k0];
            a[1] = Phi[rh * 68 + k0];
            a[2] = Phi[rl * 68 + k0 + 4];
            a[3] = Phi[rh * 68 + k0 + 4];
            #pragma unroll
            for (int nt = 0; nt < 8; nt++) {
                const int n0 = nt * 8 + r;
                MMA_TF32(oacc[nt], a, Vhi[k0 * 72 + n0], Vhi[(k0 + 4) * 72 + n0]);
            }
        }
    }

    // ---- epilogue (1.000338 compensates mean V-truncation shrinkage) ----
    const float inv0 = 1.000338f / l0, inv1 = 1.000338f / l1;
    float* o0 = out + (size_t)(b * NSEQ + q0 + rl) * CDIM + h * HDIM;
    float* o1 = out + (size_t)(b * NSEQ + q0 + rh) * CDIM + h * HDIM;
    #pragma unroll
    for (int nt = 0; nt < 8; nt++) {
        const int c = nt * 8 + tig * 2;
        float2 v0, v1;
        v0.x = oacc[nt][0] * inv0; v0.y = oacc[nt][1] * inv0;
        v1.x = oacc[nt][2] * inv1; v1.y = oacc[nt][3] * inv1;
        *(float2*)(o0 + c) = v0;
        *(float2*)(o1 + c) = v1;
    }
}

extern "C" void kernel_launch(void* const* d_in, const int* in_sizes, int n_in,
                              void* d_out, int out_size)
{
    const float* x    = (const float*)d_in[0];
    const float* w    = (const float*)d_in[1];
    const float* bias = (const float*)d_in[2];
    float* out = (float*)d_out;

    cudaFuncSetAttribute(qkv_gemm_tc,
                         cudaFuncAttributeMaxDynamicSharedMemorySize, GEMM_DSMEM);
    cudaFuncSetAttribute(attn_tc,
                         cudaFuncAttributeMaxDynamicSharedMemorySize, ATTN_DSMEM);

    qkv_gemm_tc<<<dim3(24, 64), 256, GEMM_DSMEM>>>(x, w, bias);
    // 32 q-tiles of 64 rows, B*H = 64
    attn_tc<<<dim3(32, 64), 128, ATTN_DSMEM>>>(out);
}